// round 15
// baseline (speedup 1.0000x reference)
#include <cuda_runtime.h>
#include <cstdint>

#define RPB 256
#define THREADS 512
#define SMEM_BYTES (208 * 1024 + 128)
// SMEM: A0 [0,64K), A1 [64K,128K), A2 [128K,192K), B [192K,208K), ring [208K,+12)

__device__ unsigned g_tile_ctr;

__global__ void reset_ctr_kernel() { g_tile_ctr = 0u; }

static __device__ __forceinline__ uint32_t smem_u32(const void* p) {
    uint32_t a;
    asm("{ .reg .u64 t; cvta.to.shared.u64 t, %1; cvt.u32.u64 %0, t; }" : "=r"(a) : "l"(p));
    return a;
}
static __device__ __forceinline__ uint32_t cvt_tf32(float f) {
    uint32_t r;
    asm("cvt.rn.tf32.f32 %0, %1;" : "=r"(r) : "f"(f));
    return r;
}
static __device__ __forceinline__ void mma_tf32(float* d,
    uint32_t a0, uint32_t a1, uint32_t a2, uint32_t a3,
    uint32_t b0, uint32_t b1)
{
    asm volatile("mma.sync.aligned.m16n8k8.row.col.f32.tf32.tf32.f32 "
        "{%0,%1,%2,%3}, {%4,%5,%6,%7}, {%8,%9}, {%0,%1,%2,%3};"
        : "+f"(d[0]), "+f"(d[1]), "+f"(d[2]), "+f"(d[3])
        : "r"(a0), "r"(a1), "r"(a2), "r"(a3), "r"(b0), "r"(b1));
}

// Prefetch one 256-row feature tile (raw fp32, evict-first) into a swizzled
// SMEM buffer. ALWAYS commits a group (cnt4==0 -> zero-fill, no GMEM reads).
static __device__ __forceinline__ void prefetch_tile(
    const float4* gbase, uint32_t abase, int tid, int cnt4, uint64_t pol)
{
    #pragma unroll
    for (int i = 0; i < 8; i++) {
        int idx = tid + i * THREADS;           // 0..4095
        int r = idx >> 4, c = idx & 15;
        uint32_t dst = abase + (((r << 4) | (c ^ (r & 7))) << 4);
        int cidx = (idx < cnt4) ? idx : 0;
        uint32_t sz = (idx < cnt4) ? 16u : 0u;   // OOB -> zero-fill
        asm volatile("cp.async.cg.shared.global.L2::cache_hint [%0], [%1], 16, %2, %3;"
                     :: "r"(dst), "l"(gbase + cidx), "r"(sz), "l"(pol) : "memory");
    }
    asm volatile("cp.async.commit_group;" ::: "memory");
}

// Stage 1: quad transpose (xor 1).
static __device__ __forceinline__ void quad_transpose(
    const float (&v)[8][2], float4 (&c)[4], int odd)
{
    #pragma unroll
    for (int m = 0; m < 4; m++) {
        const int j0 = 2 * m, j1 = 2 * m + 1;
        float send0 = odd ? v[j0][0] : v[j1][0];
        float send1 = odd ? v[j0][1] : v[j1][1];
        float own0  = odd ? v[j1][0] : v[j0][0];
        float own1  = odd ? v[j1][1] : v[j0][1];
        float r0 = __shfl_xor_sync(~0u, send0, 1);
        float r1 = __shfl_xor_sync(~0u, send1, 1);
        c[m].x = odd ? r0 : own0;
        c[m].y = odd ? r1 : own1;
        c[m].z = odd ? own0 : r0;
        c[m].w = odd ? own1 : r1;
    }
}

// Stage 2: xor-4 exchange of chunks {1,3}; streaming full-line stores.
static __device__ __forceinline__ void pair_store(
    float4 (&c)[4], float* op, long offE, long offO,
    int colsub, int peven, bool okE, bool okO)
{
    float4 x1, x3;
    x1.x = __shfl_xor_sync(~0u, c[1].x, 4);
    x1.y = __shfl_xor_sync(~0u, c[1].y, 4);
    x1.z = __shfl_xor_sync(~0u, c[1].z, 4);
    x1.w = __shfl_xor_sync(~0u, c[1].w, 4);
    x3.x = __shfl_xor_sync(~0u, c[3].x, 4);
    x3.y = __shfl_xor_sync(~0u, c[3].y, 4);
    x3.z = __shfl_xor_sync(~0u, c[3].z, 4);
    x3.w = __shfl_xor_sync(~0u, c[3].w, 4);
    if (okE) __stcs((float4*)(op + offE + (peven ? 0 : 16) + colsub),      peven ? c[0] : x1);
    if (okO) __stcs((float4*)(op + offO + (peven ? 16 : 0) + colsub),      peven ? x1 : c[0]);
    if (okE) __stcs((float4*)(op + offE + 32 + (peven ? 0 : 16) + colsub), peven ? c[2] : x3);
    if (okO) __stcs((float4*)(op + offO + 32 + (peven ? 16 : 0) + colsub), peven ? x3 : c[2]);
}

// Persistent, 1 CTA/SM (512 thr, 16 warps), triple-buffered 64KB tiles,
// atomic tile stealing.
__global__ __launch_bounds__(THREADS, 1) void assign_mma_kernel(
    const float4* __restrict__ feat4,
    const float4* __restrict__ proto4,
    float* __restrict__ out, int nrows, int ntiles)
{
    extern __shared__ char smem[];
    const uint32_t sbase = smem_u32(smem);
    uint4* B_s = (uint4*)(smem + 192 * 1024);
    int* ring = (int*)(smem + 208 * 1024);   // 3 tile ids

    const int tid = threadIdx.x;
    const int w = tid >> 5, lane = tid & 31;
    const int gid = lane >> 2, tig = lane & 3;
    const int odd = tig & 1, tigh = tig >> 1;
    const int colsub = 4 * (tigh + 2 * odd);
    const int peven = ((gid & 1) == 0);
    const int sw = gid << 2;
    const int rb = w * 16;

    uint64_t pol;
    asm("createpolicy.fractional.L2::evict_first.b64 %0, 1.0;" : "=l"(pol));

    // ---- stage prototypes once (tf32, swizzled) + steal first 3 tiles ----
    if (tid == 0) {
        unsigned t = atomicAdd(&g_tile_ctr, 3u);
        ring[0] = (int)t; ring[1] = (int)(t + 1); ring[2] = (int)(t + 2);
    }
    #pragma unroll
    for (int i = 0; i < 2; i++) {
        int idx = tid + i * THREADS;
        float4 v = proto4[idx];
        uint4 t;
        t.x = cvt_tf32(v.x); t.y = cvt_tf32(v.y);
        t.z = cvt_tf32(v.z); t.w = cvt_tf32(v.w);
        int n = idx >> 4, c = idx & 15;
        B_s[(n << 4) | (c ^ (n & 7))] = t;
    }
    __syncthreads();
    const uint32_t* Bs32 = (const uint32_t*)B_s;

    // ---- prologue: prefetch ring[0] -> slot0, ring[1] -> slot1 ----
    {
        int t0 = ring[0], t1 = ring[1];
        long c0 = (t0 < ntiles) ? (long)t0 : (long)(ntiles - 1);
        int n0 = (t0 < ntiles) ? min(RPB, nrows - (int)(c0 * RPB)) * 16 : 0;
        prefetch_tile(feat4 + c0 * RPB * 16, sbase, tid, n0, pol);
        long c1 = (t1 < ntiles) ? (long)t1 : (long)(ntiles - 1);
        int n1 = (t1 < ntiles) ? min(RPB, nrows - (int)(c1 * RPB)) * 16 : 0;
        prefetch_tile(feat4 + c1 * RPB * 16, sbase + (1u << 16), tid, n1, pol);
    }

    int cs = 0;   // compute slot (rotates 0,1,2)
    int ps = 2;   // prefetch slot = (cs+2)%3
    int cur = ring[0];
    while (cur < ntiles) {
        const long base = (long)cur * RPB;
        const int rows = min(RPB, nrows - (int)base);

        // prefetch ring[ps] into slot ps — always commit a group
        {
            int tn = ring[ps];
            long tc = (tn < ntiles) ? (long)tn : (long)(ntiles - 1);
            int cnt = (tn < ntiles) ? min(RPB, nrows - (int)(tc * RPB)) * 16 : 0;
            prefetch_tile(feat4 + tc * RPB * 16, sbase + ((uint32_t)ps << 16), tid, cnt, pol);
        }
        // two younger groups pending -> current tile's group drained
        asm volatile("cp.async.wait_group 2;" ::: "memory");
        __syncthreads();

        const float* Asf = (const float*)(smem + ((uint32_t)cs << 16));

        // ---- GEMM + fused row norms (raw fp32 -> cvt at use) ----
        float acc[8][4];
        float nrm[2] = {0.f, 0.f};
        #pragma unroll
        for (int j = 0; j < 8; j++)
            #pragma unroll
            for (int e = 0; e < 4; e++) acc[j][e] = 0.f;

        #pragma unroll
        for (int ks = 0; ks < 8; ks++) {
            int o0 = (ks * 8 + tig) ^ sw;
            int o1 = (ks * 8 + tig + 4) ^ sw;
            int r = rb + gid;
            float f0 = Asf[r * 64 + o0];
            float f1 = Asf[(r + 8) * 64 + o0];
            float f2 = Asf[r * 64 + o1];
            float f3 = Asf[(r + 8) * 64 + o1];
            nrm[0] += f0 * f0 + f2 * f2;   // row r
            nrm[1] += f1 * f1 + f3 * f3;   // row r+8
            uint32_t a0 = cvt_tf32(f0), a1 = cvt_tf32(f1);
            uint32_t a2 = cvt_tf32(f2), a3 = cvt_tf32(f3);
            #pragma unroll
            for (int j = 0; j < 8; j++) {
                int n = j * 8 + gid;
                mma_tf32(acc[j], a0, a1, a2, a3,
                         Bs32[n * 64 + o0], Bs32[n * 64 + o1]);
            }
        }

        // steal replacement tile for the slot being consumed; latency hides
        // under the epilogue, published by the end-of-iteration barrier
        if (tid == 0) ring[cs] = (int)atomicAdd(&g_tile_ctr, 1u);

        // ---- scales: quad-reduce; sc = 5 / max(||f||, eps)  (tau=0.2) ----
        float sc[2];
        #pragma unroll
        for (int hf = 0; hf < 2; hf++) {
            float s = nrm[hf];
            s += __shfl_xor_sync(~0u, s, 1);
            s += __shfl_xor_sync(~0u, s, 2);
            sc[hf] = 5.0f / fmaxf(sqrtf(s), 1e-8f);
        }

        // ---- epilogue ----
        #pragma unroll
        for (int hf = 0; hf < 2; hf++) {
            int rE = rb + hf * 8 + (gid & ~1);
            int rO = rE + 1;
            float scv = sc[hf];
            bool okE = (rE < rows), okO = (rO < rows);
            long offE = (base + rE) * 64;
            long offO = (base + rO) * 64;

            float lg[8][2], ex[8][2];
            float s = 0.f;
            #pragma unroll
            for (int j = 0; j < 8; j++) {
                lg[j][0] = acc[j][2 * hf]     * scv;
                lg[j][1] = acc[j][2 * hf + 1] * scv;
                ex[j][0] = __expf(lg[j][0]);       // |logit| <= 5
                ex[j][1] = __expf(lg[j][1]);
                s += ex[j][0] + ex[j][1];
            }
            s += __shfl_xor_sync(~0u, s, 1);
            s += __shfl_xor_sync(~0u, s, 2);
            float inv = 1.0f / s;
            #pragma unroll
            for (int j = 0; j < 8; j++) {
                ex[j][0] *= inv;
                ex[j][1] *= inv;
            }

            float4 c[4];
            quad_transpose(lg, c, odd);
            pair_store(c, out, offE, offO, colsub, peven, okE, okO);
            quad_transpose(ex, c, odd);
            pair_store(c, out + (long)nrows * 64, offE, offO, colsub, peven, okE, okO);
        }
        __syncthreads();   // slot-cs reads done + ring[cs] published

        cs = (cs + 1 == 3) ? 0 : cs + 1;
        ps = (ps + 1 == 3) ? 0 : ps + 1;
        cur = ring[cs];
    }
    // drain outstanding async copies before exit
    asm volatile("cp.async.wait_group 0;" ::: "memory");
}

extern "C" void kernel_launch(void* const* d_in, const int* in_sizes, int n_in,
                              void* d_out, int out_size) {
    const float4* feat4  = (const float4*)d_in[0];
    const float4* proto4 = (const float4*)d_in[1];
    float* out = (float*)d_out;
    int nrows = in_sizes[0] / 64;
    int ntiles = (nrows + RPB - 1) / RPB;
    cudaFuncSetAttribute(assign_mma_kernel,
                         cudaFuncAttributeMaxDynamicSharedMemorySize, SMEM_BYTES);
    reset_ctr_kernel<<<1, 1>>>();
    int grid = 148;                    // 1 persistent CTA per SM
    if (grid > ntiles) grid = ntiles;
    assign_mma_kernel<<<grid, THREADS, SMEM_BYTES>>>(feat4, proto4, out, nrows, ntiles);
}

// round 16
// speedup vs baseline: 1.1209x; 1.1209x over previous
#include <cuda_runtime.h>
#include <cstdint>

#define RPB 128
#define THREADS 256
#define SMEM_BYTES (112 * 1024 + 128)
// SMEM: A0 [0,32K), A1 [32K,64K), A2 [64K,96K), B [96K,112K), tile ring [112K,+12)

__device__ unsigned g_tile_ctr;

__global__ void reset_ctr_kernel() { g_tile_ctr = 0u; }

static __device__ __forceinline__ uint32_t smem_u32(const void* p) {
    uint32_t a;
    asm("{ .reg .u64 t; cvta.to.shared.u64 t, %1; cvt.u32.u64 %0, t; }" : "=r"(a) : "l"(p));
    return a;
}
static __device__ __forceinline__ uint32_t cvt_tf32(float f) {
    uint32_t r;
    asm("cvt.rn.tf32.f32 %0, %1;" : "=r"(r) : "f"(f));
    return r;
}
static __device__ __forceinline__ void mma_tf32(float* d,
    uint32_t a0, uint32_t a1, uint32_t a2, uint32_t a3,
    uint32_t b0, uint32_t b1)
{
    asm volatile("mma.sync.aligned.m16n8k8.row.col.f32.tf32.tf32.f32 "
        "{%0,%1,%2,%3}, {%4,%5,%6,%7}, {%8,%9}, {%0,%1,%2,%3};"
        : "+f"(d[0]), "+f"(d[1]), "+f"(d[2]), "+f"(d[3])
        : "r"(a0), "r"(a1), "r"(a2), "r"(a3), "r"(b0), "r"(b1));
}

// Prefetch one 128-row feature tile (raw fp32, evict-first) into a swizzled
// SMEM buffer. ALWAYS commits a group (cnt4==0 -> zero-fill, no GMEM reads).
static __device__ __forceinline__ void prefetch_tile(
    const float4* gbase, uint32_t abase, int tid, int cnt4, uint64_t pol)
{
    #pragma unroll
    for (int i = 0; i < 8; i++) {
        int idx = tid + i * THREADS;
        int r = idx >> 4, c = idx & 15;
        uint32_t dst = abase + (((r << 4) | (c ^ (r & 7))) << 4);
        int cidx = (idx < cnt4) ? idx : 0;
        uint32_t sz = (idx < cnt4) ? 16u : 0u;       // OOB -> zero-fill
        asm volatile("cp.async.cg.shared.global.L2::cache_hint [%0], [%1], 16, %2, %3;"
                     :: "r"(dst), "l"(gbase + cidx), "r"(sz), "l"(pol) : "memory");
    }
    asm volatile("cp.async.commit_group;" ::: "memory");
}

// Stage 1: quad transpose (xor 1).
static __device__ __forceinline__ void quad_transpose(
    const float (&v)[8][2], float4 (&c)[4], int odd)
{
    #pragma unroll
    for (int m = 0; m < 4; m++) {
        const int j0 = 2 * m, j1 = 2 * m + 1;
        float send0 = odd ? v[j0][0] : v[j1][0];
        float send1 = odd ? v[j0][1] : v[j1][1];
        float own0  = odd ? v[j1][0] : v[j0][0];
        float own1  = odd ? v[j1][1] : v[j0][1];
        float r0 = __shfl_xor_sync(~0u, send0, 1);
        float r1 = __shfl_xor_sync(~0u, send1, 1);
        c[m].x = odd ? r0 : own0;
        c[m].y = odd ? r1 : own1;
        c[m].z = odd ? own0 : r0;
        c[m].w = odd ? own1 : r1;
    }
}

// Stage 2: xor-4 exchange of chunks {1,3}; streaming full-line stores.
static __device__ __forceinline__ void pair_store(
    float4 (&c)[4], float* op, long offE, long offO,
    int colsub, int peven, bool okE, bool okO)
{
    float4 x1, x3;
    x1.x = __shfl_xor_sync(~0u, c[1].x, 4);
    x1.y = __shfl_xor_sync(~0u, c[1].y, 4);
    x1.z = __shfl_xor_sync(~0u, c[1].z, 4);
    x1.w = __shfl_xor_sync(~0u, c[1].w, 4);
    x3.x = __shfl_xor_sync(~0u, c[3].x, 4);
    x3.y = __shfl_xor_sync(~0u, c[3].y, 4);
    x3.z = __shfl_xor_sync(~0u, c[3].z, 4);
    x3.w = __shfl_xor_sync(~0u, c[3].w, 4);
    if (okE) __stcs((float4*)(op + offE + (peven ? 0 : 16) + colsub),      peven ? c[0] : x1);
    if (okO) __stcs((float4*)(op + offO + (peven ? 16 : 0) + colsub),      peven ? x1 : c[0]);
    if (okE) __stcs((float4*)(op + offE + 32 + (peven ? 0 : 16) + colsub), peven ? c[2] : x3);
    if (okO) __stcs((float4*)(op + offO + 32 + (peven ? 16 : 0) + colsub), peven ? x3 : c[2]);
}

// Persistent, 2 CTAs/SM, triple-buffered cp.async pipeline, atomic tile stealing.
__global__ __launch_bounds__(THREADS, 2) void assign_mma_kernel(
    const float4* __restrict__ feat4,
    const float4* __restrict__ proto4,
    float* __restrict__ out, int nrows, int ntiles)
{
    extern __shared__ char smem[];
    const uint32_t sbase = smem_u32(smem);
    uint4* B_s = (uint4*)(smem + 96 * 1024);
    int* ring = (int*)(smem + 112 * 1024);   // 3 tile ids

    const int tid = threadIdx.x;
    const int w = tid >> 5, lane = tid & 31;
    const int gid = lane >> 2, tig = lane & 3;
    const int odd = tig & 1, tigh = tig >> 1;
    const int colsub = 4 * (tigh + 2 * odd);
    const int peven = ((gid & 1) == 0);
    const int sw = gid << 2;
    const int rb = w * 16;

    uint64_t pol;
    asm("createpolicy.fractional.L2::evict_first.b64 %0, 1.0;" : "=l"(pol));

    // ---- stage prototypes once (tf32, swizzled) + steal first 3 tiles ----
    if (tid == 0) {
        unsigned t = atomicAdd(&g_tile_ctr, 3u);
        ring[0] = (int)t; ring[1] = (int)(t + 1); ring[2] = (int)(t + 2);
    }
    #pragma unroll
    for (int i = 0; i < 4; i++) {
        int idx = tid + i * THREADS;
        float4 v = proto4[idx];
        uint4 t;
        t.x = cvt_tf32(v.x); t.y = cvt_tf32(v.y);
        t.z = cvt_tf32(v.z); t.w = cvt_tf32(v.w);
        int n = idx >> 4, c = idx & 15;
        B_s[(n << 4) | (c ^ (n & 7))] = t;
    }
    __syncthreads();
    const uint32_t* Bs32 = (const uint32_t*)B_s;

    // ---- prologue: prefetch ring[0] -> slot0, ring[1] -> slot1 ----
    {
        int t0 = ring[0], t1 = ring[1];
        long c0 = (t0 < ntiles) ? (long)t0 : (long)(ntiles - 1);
        int n0 = (t0 < ntiles) ? min(RPB, nrows - (int)(c0 * RPB)) * 16 : 0;
        prefetch_tile(feat4 + c0 * RPB * 16, sbase, tid, n0, pol);
        long c1 = (t1 < ntiles) ? (long)t1 : (long)(ntiles - 1);
        int n1 = (t1 < ntiles) ? min(RPB, nrows - (int)(c1 * RPB)) * 16 : 0;
        prefetch_tile(feat4 + c1 * RPB * 16, sbase + (1u << 15), tid, n1, pol);
    }

    int cs = 0;   // compute slot (rotates 0,1,2)
    int ps = 2;   // prefetch slot = (cs+2)%3
    int cur = ring[0];
    while (cur < ntiles) {
        const long base = (long)cur * RPB;
        const int rows = min(RPB, nrows - (int)base);

        // prefetch ring[ps] into slot ps — always commit a group
        {
            int tn = ring[ps];
            long tc = (tn < ntiles) ? (long)tn : (long)(ntiles - 1);
            int cnt = (tn < ntiles) ? min(RPB, nrows - (int)(tc * RPB)) * 16 : 0;
            prefetch_tile(feat4 + tc * RPB * 16, sbase + ((uint32_t)ps << 15), tid, cnt, pol);
        }
        // two younger groups pending -> current tile's group drained
        asm volatile("cp.async.wait_group 2;" ::: "memory");
        __syncthreads();

        const float* Asf = (const float*)(smem + ((uint32_t)cs << 15));

        // ---- GEMM + fused row norms (raw fp32 -> cvt at use) ----
        float acc[8][4];
        float nrm[2] = {0.f, 0.f};
        #pragma unroll
        for (int j = 0; j < 8; j++)
            #pragma unroll
            for (int e = 0; e < 4; e++) acc[j][e] = 0.f;

        #pragma unroll
        for (int ks = 0; ks < 8; ks++) {
            int o0 = (ks * 8 + tig) ^ sw;
            int o1 = (ks * 8 + tig + 4) ^ sw;
            int r = rb + gid;
            float f0 = Asf[r * 64 + o0];
            float f1 = Asf[(r + 8) * 64 + o0];
            float f2 = Asf[r * 64 + o1];
            float f3 = Asf[(r + 8) * 64 + o1];
            nrm[0] += f0 * f0 + f2 * f2;   // row r
            nrm[1] += f1 * f1 + f3 * f3;   // row r+8
            uint32_t a0 = cvt_tf32(f0), a1 = cvt_tf32(f1);
            uint32_t a2 = cvt_tf32(f2), a3 = cvt_tf32(f3);
            #pragma unroll
            for (int j = 0; j < 8; j++) {
                int n = j * 8 + gid;
                mma_tf32(acc[j], a0, a1, a2, a3,
                         Bs32[n * 64 + o0], Bs32[n * 64 + o1]);
            }
        }

        // steal replacement tile for the slot being consumed; latency hides
        // under the epilogue, published by the end-of-iteration barrier
        if (tid == 0) ring[cs] = (int)atomicAdd(&g_tile_ctr, 1u);

        // ---- scales: quad-reduce; sc = 5 / max(||f||, eps)  (tau=0.2) ----
        float sc[2];
        #pragma unroll
        for (int hf = 0; hf < 2; hf++) {
            float s = nrm[hf];
            s += __shfl_xor_sync(~0u, s, 1);
            s += __shfl_xor_sync(~0u, s, 2);
            sc[hf] = 5.0f / fmaxf(sqrtf(s), 1e-8f);
        }

        // ---- epilogue ----
        #pragma unroll
        for (int hf = 0; hf < 2; hf++) {
            int rE = rb + hf * 8 + (gid & ~1);
            int rO = rE + 1;
            float scv = sc[hf];
            bool okE = (rE < rows), okO = (rO < rows);
            long offE = (base + rE) * 64;
            long offO = (base + rO) * 64;

            float lg[8][2], ex[8][2];
            float s = 0.f;
            #pragma unroll
            for (int j = 0; j < 8; j++) {
                lg[j][0] = acc[j][2 * hf]     * scv;
                lg[j][1] = acc[j][2 * hf + 1] * scv;
                ex[j][0] = __expf(lg[j][0]);       // |logit| <= 5
                ex[j][1] = __expf(lg[j][1]);
                s += ex[j][0] + ex[j][1];
            }
            s += __shfl_xor_sync(~0u, s, 1);
            s += __shfl_xor_sync(~0u, s, 2);
            float inv = 1.0f / s;
            #pragma unroll
            for (int j = 0; j < 8; j++) {
                ex[j][0] *= inv;
                ex[j][1] *= inv;
            }

            float4 c[4];
            quad_transpose(lg, c, odd);
            pair_store(c, out, offE, offO, colsub, peven, okE, okO);
            quad_transpose(ex, c, odd);
            pair_store(c, out + (long)nrows * 64, offE, offO, colsub, peven, okE, okO);
        }
        __syncthreads();   // slot-cs reads done + ring[cs] published

        cs = (cs + 1 == 3) ? 0 : cs + 1;
        ps = (ps + 1 == 3) ? 0 : ps + 1;
        cur = ring[cs];
    }
    // drain outstanding async copies before exit
    asm volatile("cp.async.wait_group 0;" ::: "memory");
}

extern "C" void kernel_launch(void* const* d_in, const int* in_sizes, int n_in,
                              void* d_out, int out_size) {
    const float4* feat4  = (const float4*)d_in[0];
    const float4* proto4 = (const float4*)d_in[1];
    float* out = (float*)d_out;
    int nrows = in_sizes[0] / 64;
    int ntiles = (nrows + RPB - 1) / RPB;
    cudaFuncSetAttribute(assign_mma_kernel,
                         cudaFuncAttributeMaxDynamicSharedMemorySize, SMEM_BYTES);
    reset_ctr_kernel<<<1, 1>>>();
    int grid = 296;                    // 2 persistent CTAs per SM (148 SMs)
    if (grid > ntiles) grid = ntiles;
    assign_mma_kernel<<<grid, THREADS, SMEM_BYTES>>>(feat4, proto4, out, nrows, ntiles);
}